// round 2
// baseline (speedup 1.0000x reference)
#include <cuda_runtime.h>

// HyperMLP: per-sample MLP 128 -> 512 -> 512 -> 512 -> 128, relu between.
// z[b] holds (w1,b1,w2,b2,w3,b3,w4,b4) flattened, w row-major [din][dout].
// Pure HBM-streaming problem: 1.346 GB of weights read once.

#define NBATCH 512
#define TOTAL_PARAMS 657024

// Param offsets within one sample's z row (floats):
#define W1_OFF 0          // 128*512
#define B1_OFF 65536      // 512
#define W2_OFF 66048      // 512*512
#define B2_OFF 328192     // 512
#define W3_OFF 328704     // 512*512
#define B3_OFF 590848     // 512
#define W4_OFF 591360     // 512*128
#define B4_OFF 656896     // 128

__global__ __launch_bounds__(512, 4)
void hypermlp_kernel(const float* __restrict__ z,
                     const float* __restrict__ xq,
                     float* __restrict__ out)
{
    const int b = blockIdx.x;
    const float* __restrict__ zb = z + (size_t)b * TOTAL_PARAMS;
    const int t = threadIdx.x;           // 0..511

    __shared__ float xs[512];            // activations (max width 512)
    __shared__ float red[4 * 512];       // 8KB partial-sum buffer

    // Load input x_q[b, 0:128]
    if (t < 128) xs[t] = xq[b * 128 + t];
    __syncthreads();

    // ---------------- Layer 1: din=128, dout=512 ----------------
    {
        const float4* __restrict__ wv = (const float4*)(zb + W1_OFF);
        const float* __restrict__ bias = zb + B1_OFF;
        const int lane = t & 127;        // output quad index (o = lane*4..+3)
        const int g    = t >> 7;         // i-slice 0..3 (32 rows each)
        float4 acc = make_float4(0.f, 0.f, 0.f, 0.f);
        #pragma unroll 8
        for (int i = g * 32; i < g * 32 + 32; ++i) {
            const float xi = xs[i];
            const float4 wq = __ldcs(&wv[i * 128 + lane]);
            acc.x = fmaf(xi, wq.x, acc.x);
            acc.y = fmaf(xi, wq.y, acc.y);
            acc.z = fmaf(xi, wq.z, acc.z);
            acc.w = fmaf(xi, wq.w, acc.w);
        }
        ((float4*)(red + g * 512))[lane] = acc;
        __syncthreads();
        float s = red[0 * 512 + t] + red[1 * 512 + t]
                + red[2 * 512 + t] + red[3 * 512 + t] + bias[t];
        s = fmaxf(s, 0.f);
        xs[t] = s;                       // safe: all xs reads done before prior sync
        __syncthreads();
    }

    // ---------------- Layers 2 & 3: din=512, dout=512 ----------------
    {
        const float* p = zb + W2_OFF;
        #pragma unroll 1
        for (int L = 0; L < 2; ++L) {
            const float4* __restrict__ wv = (const float4*)p;
            const float* __restrict__ bias = p + 512 * 512;
            const int lane = t & 127;
            const int g    = t >> 7;     // 4 slices x 128 rows
            float4 acc = make_float4(0.f, 0.f, 0.f, 0.f);
            #pragma unroll 8
            for (int i = g * 128; i < g * 128 + 128; ++i) {
                const float xi = xs[i];
                const float4 wq = __ldcs(&wv[i * 128 + lane]);
                acc.x = fmaf(xi, wq.x, acc.x);
                acc.y = fmaf(xi, wq.y, acc.y);
                acc.z = fmaf(xi, wq.z, acc.z);
                acc.w = fmaf(xi, wq.w, acc.w);
            }
            ((float4*)(red + g * 512))[lane] = acc;
            __syncthreads();
            float s = red[0 * 512 + t] + red[1 * 512 + t]
                    + red[2 * 512 + t] + red[3 * 512 + t] + bias[t];
            s = fmaxf(s, 0.f);
            xs[t] = s;
            __syncthreads();
            p += 512 * 512 + 512;
        }
    }

    // ---------------- Layer 4: din=512, dout=128 (no relu) ----------------
    {
        const float4* __restrict__ wv = (const float4*)(zb + W4_OFF);
        const float* __restrict__ bias = zb + B4_OFF;
        const int lane = t & 31;         // output quad (o = lane*4..+3), 32 lanes
        const int g    = t >> 5;         // 16 i-slices x 32 rows
        float4 acc = make_float4(0.f, 0.f, 0.f, 0.f);
        #pragma unroll 8
        for (int i = g * 32; i < g * 32 + 32; ++i) {
            const float xi = xs[i];
            const float4 wq = __ldcs(&wv[i * 32 + lane]);
            acc.x = fmaf(xi, wq.x, acc.x);
            acc.y = fmaf(xi, wq.y, acc.y);
            acc.z = fmaf(xi, wq.z, acc.z);
            acc.w = fmaf(xi, wq.w, acc.w);
        }
        // red reused as [16][128]
        ((float4*)(red + g * 128))[lane] = acc;
        __syncthreads();
        if (t < 128) {
            float s = bias[t];
            #pragma unroll
            for (int g2 = 0; g2 < 16; ++g2) s += red[g2 * 128 + t];
            out[b * 128 + t] = s;
        }
    }
}

extern "C" void kernel_launch(void* const* d_in, const int* in_sizes, int n_in,
                              void* d_out, int out_size)
{
    // Inputs per metadata order: z (512*657024 f32), x_q (512*128 f32).
    // Defensive swap by size in case order differs.
    const float* z  = (const float*)d_in[0];
    const float* xq = (const float*)d_in[1];
    if (n_in >= 2 && in_sizes[0] == NBATCH * 128) {
        z  = (const float*)d_in[1];
        xq = (const float*)d_in[0];
    }
    float* out = (float*)d_out;
    hypermlp_kernel<<<NBATCH, 512>>>(z, xq, out);
}